// round 10
// baseline (speedup 1.0000x reference)
#include <cuda_runtime.h>

#define D      128
#define KS     9
#define L_IN   4096
#define L_OUT  4072
#define T_EFF  25
#define T12    17
#define BATCH  128
#define GRID   128
#define ROW    (D * KS)   // 1152

// Inter-phase tables (transposed: channel contiguous -> coalesced reads)
__device__ float d_g1T[36 * D];        // [(v*9+k1)][c1]
__device__ float d_g2T[68 * D];        // [(v*17+t12)][c2]
__device__ float d_G  [100 * D];       // [(t*4+v)][c]
__device__ float d_bb2[D];
__device__ float d_beff[D];

// Grid-barrier state (generation counters are monotonic across replays)
__device__ unsigned g_cnt[4];
__device__ unsigned g_gen[4];

__device__ __forceinline__ void grid_sync(int k) {
    __syncthreads();
    if (threadIdx.x == 0) {
        __threadfence();
        volatile unsigned* vg = g_gen;
        unsigned g = vg[k];
        unsigned old = atomicAdd(&g_cnt[k], 1u);
        if (old == GRID - 1) {
            g_cnt[k] = 0;
            __threadfence();
            atomicAdd(&g_gen[k], 1u);
        } else {
            while (vg[k] == g) { }
        }
        __threadfence();
    }
    __syncthreads();
}

__device__ __forceinline__ float warp_sum(float s) {
    #pragma unroll
    for (int o = 16; o; o >>= 1) s += __shfl_xor_sync(0xffffffffu, s, o);
    return s;
}

// ---------------------------------------------------------------------------
// Fused pre: P1 (g1T) -> sync -> P2 (g2T+bb2) -> sync -> P3 (G+beff).
__global__ __launch_bounds__(1024) void k_pre(
    const float* __restrict__ w1, const float* __restrict__ emb,
    const float* __restrict__ w2, const float* __restrict__ b1,
    const float* __restrict__ b2,
    const float* __restrict__ w3, const float* __restrict__ b3)
{
    __shared__ float ws[ROW];
    __shared__ float es[4 * D];
    const int bid = blockIdx.x, tid = threadIdx.x;
    const int lane = tid & 31, warp = tid >> 5;

    // ---- P1: c1 = bid
    {
        const float* wrow = w1 + bid * ROW;
        for (int i = tid; i < ROW; i += 1024) ws[i] = wrow[i];
        if (tid < 512) es[tid] = emb[tid];
        __syncthreads();
        for (int pr = warp; pr < 36; pr += 32) {
            const int v = pr / KS, k1 = pr % KS;
            float s = 0.f;
            #pragma unroll
            for (int m = 0; m < 4; m++) {
                int c0 = lane + 32 * m;
                s += ws[c0 * KS + k1] * es[v * D + c0];
            }
            s = warp_sum(s);
            if (lane == 0) d_g1T[pr * D + bid] = s;
        }
    }
    grid_sync(0);

    // ---- P2: c2 = bid
    {
        const float* wrow = w2 + bid * ROW;
        __syncthreads();   // ws reuse: all P1 readers done (same CTA)
        for (int i = tid; i < ROW; i += 1024) ws[i] = wrow[i];
        __syncthreads();
        for (int pr = warp; pr < 69; pr += 32) {
            if (pr < 68) {
                const int v = pr / T12, t = pr % T12;
                const int klo = (t > KS - 1) ? t - (KS - 1) : 0;
                const int khi = (t < KS - 1) ? t : KS - 1;
                float s = 0.f;
                for (int k2 = klo; k2 <= khi; k2++) {
                    const int k1 = t - k2;
                    const float* g1r = d_g1T + (v * KS + k1) * D;
                    #pragma unroll
                    for (int m = 0; m < 4; m++) {
                        int c1 = lane + 32 * m;
                        s += ws[c1 * KS + k2] * g1r[c1];
                    }
                }
                s = warp_sum(s);
                if (lane == 0) d_g2T[(v * T12 + t) * D + bid] = s;
            } else {
                float s = 0.f;
                #pragma unroll 4
                for (int i = 0; i < 36; i++) {
                    int idx = lane + 32 * i;
                    s += ws[idx] * b1[idx / KS];
                }
                s = warp_sum(s);
                if (lane == 0) d_bb2[bid] = b2[bid] + s;
            }
        }
    }
    grid_sync(1);

    // ---- P3: c3 = bid
    {
        const float* wrow = w3 + bid * ROW;
        __syncthreads();
        for (int i = tid; i < ROW; i += 1024) ws[i] = wrow[i];
        __syncthreads();
        for (int pr = warp; pr < 101; pr += 32) {
            if (pr < 100) {
                const int v = pr & 3, t = pr >> 2;
                const int klo = (t > T12 - 1) ? t - (T12 - 1) : 0;
                const int khi = (t < KS - 1) ? t : KS - 1;
                float s = 0.f;
                for (int k3 = klo; k3 <= khi; k3++) {
                    const int t12 = t - k3;
                    const float* g2r = d_g2T + (v * T12 + t12) * D;
                    #pragma unroll
                    for (int m = 0; m < 4; m++) {
                        int c2 = lane + 32 * m;
                        s += ws[c2 * KS + k3] * g2r[c2];
                    }
                }
                s = warp_sum(s);
                if (lane == 0) d_G[(t * 4 + v) * D + bid] = s;
            } else {
                float s = 0.f;
                #pragma unroll 4
                for (int i = 0; i < 36; i++) {
                    int idx = lane + 32 * i;
                    s += ws[idx] * d_bb2[idx / KS];
                }
                s = warp_sum(s);
                if (lane == 0) d_beff[bid] = b3[bid] + s;
            }
        }
    }
}

// ---------------------------------------------------------------------------
// Main kernel: one CTA per batch row. Projections applied as in-CTA matvecs.
__global__ __launch_bounds__(1024) void k_main(
    const int*   __restrict__ tokens,
    const float* __restrict__ wq, const float* __restrict__ bq,
    const float* __restrict__ wk,
    const float* __restrict__ wv, const float* __restrict__ bv,
    float* __restrict__ out)
{
    __shared__ __align__(16) float sc[4096];
    __shared__ float Hq[6 * 256];
    __shared__ float Hs[128];
    __shared__ float As[128];
    __shared__ float cntf[128];
    __shared__ float rm[128];
    __shared__ float qv[128];
    __shared__ float kq[128];
    __shared__ float sv[128];
    __shared__ float part[7 * 4 * 12];
    __shared__ float redf[40];
    __shared__ int   cnti[4];
    __shared__ unsigned tok_u[1032];
    __shared__ unsigned pat_u[1032];
    unsigned char* tok = (unsigned char*)tok_u;

    const int b = blockIdx.x, tid = threadIdx.x;
    const int lane = tid & 31, warp = tid >> 5;

    // scores scale folded into Hs: SCL = (1/sqrt(128)) * log2(e)
    const float SCL = 0.088388347648318447f * 1.4426950408889634f;

    // tokens -> packed bytes
    {
        const int4* tb4 = (const int4*)(tokens + b * L_IN);
        int4 w = tb4[tid];
        tok_u[tid] = (unsigned)w.x | ((unsigned)w.y << 8) |
                     ((unsigned)w.z << 16) | ((unsigned)w.w << 24);
    }
    if (tid < 8) tok_u[1024 + tid] = 0;
    if (tid < 4) cnti[tid] = 0;
    __syncthreads();

    // quad patterns
    for (int i = tid; i < 1030; i += 1024) {
        unsigned w0 = tok_u[i], w1w = tok_u[i + 1];
        unsigned p0 = ((w0 & 0x03030303u) * 0x40100401u) >> 24;
        unsigned f1 = __funnelshift_r(w0, w1w, 8);
        unsigned p1 = ((f1 & 0x03030303u) * 0x40100401u) >> 24;
        unsigned f2 = __funnelshift_r(w0, w1w, 16);
        unsigned p2 = ((f2 & 0x03030303u) * 0x40100401u) >> 24;
        unsigned f3 = __funnelshift_r(w0, w1w, 24);
        unsigned p3 = ((f3 & 0x03030303u) * 0x40100401u) >> 24;
        pat_u[i] = p0 | (p1 << 8) | (p2 << 16) | (p3 << 24);
    }

    // full counts
    {
        unsigned u = tok_u[tid];
        int l0 = 0, l1 = 0, l2 = 0, l3 = 0;
        #pragma unroll
        for (int j = 0; j < 4; j++) {
            int v = (u >> (8 * j)) & 3;
            l0 += (v == 0); l1 += (v == 1); l2 += (v == 2); l3 += (v == 3);
        }
        #pragma unroll
        for (int o = 16; o; o >>= 1) {
            l0 += __shfl_xor_sync(0xffffffffu, l0, o);
            l1 += __shfl_xor_sync(0xffffffffu, l1, o);
            l2 += __shfl_xor_sync(0xffffffffu, l2, o);
            l3 += __shfl_xor_sync(0xffffffffu, l3, o);
        }
        if (lane == 0) {
            atomicAdd(&cnti[0], l0); atomicAdd(&cnti[1], l1);
            atomicAdd(&cnti[2], l2); atomicAdd(&cnti[3], l3);
        }
    }
    __syncthreads();

    // windowed counts
    if (warp == 0 && lane < T_EFF) {
        int t = lane;
        int c0 = cnti[0], c1 = cnti[1], c2 = cnti[2], c3 = cnti[3];
        for (int j = 0; j < t; j++) {
            int v = tok[j];
            c0 -= (v == 0); c1 -= (v == 1); c2 -= (v == 2); c3 -= (v == 3);
        }
        for (int j = t + L_OUT; j < L_IN; j++) {
            int v = tok[j];
            c0 -= (v == 0); c1 -= (v == 1); c2 -= (v == 2); c3 -= (v == 3);
        }
        cntf[t * 4 + 0] = (float)c0; cntf[t * 4 + 1] = (float)c1;
        cntf[t * 4 + 2] = (float)c2; cntf[t * 4 + 3] = (float)c3;
    }
    __syncthreads();

    // rm[x] = beff[x] + (1/L) * sum_i cnt_i * G[i][x]
    {
        int pt = tid >> 7, x = tid & 127;
        int i0 = pt * 13, i1 = (pt == 7) ? 100 : i0 + 13;
        float acc = 0.f;
        for (int i = i0; i < i1; i++) acc += cntf[i] * d_G[i * D + x];
        sc[pt * 128 + x] = acc;
    }
    __syncthreads();
    if (tid < D) {
        float acc = 0.f;
        #pragma unroll
        for (int p = 0; p < 8; p++) acc += sc[p * 128 + tid];
        rm[tid] = d_beff[tid] + acc * (1.0f / (float)L_OUT);
    }
    __syncthreads();

    // q = Wq @ rm + bq
    for (int c = warp; c < D; c += 32) {
        float s = 0.f;
        #pragma unroll
        for (int m = 0; m < 4; m++) { int x = lane + 32 * m; s += wq[c * D + x] * rm[x]; }
        s = warp_sum(s);
        if (lane == 0) qv[c] = s + bq[c];
    }
    __syncthreads();

    // kq[x] = sum_c Wk[c][x] * q[c]
    {
        int g = tid >> 7, x = tid & 127;
        float s = 0.f;
        #pragma unroll
        for (int o = 0; o < 16; o++) s += wk[(g * 16 + o) * D + x] * qv[g * 16 + o];
        sc[g * D + x] = s;
    }
    __syncthreads();
    if (tid < D) {
        float s = 0.f;
        #pragma unroll
        for (int g = 0; g < 8; g++) s += sc[g * D + tid];
        kq[tid] = s;
    }
    __syncthreads();

    // Hs[i] = SCL * (G[i,:] . kq)   -- scale folded in here
    for (int i = warp; i < 100; i += 32) {
        float s = 0.f;
        #pragma unroll
        for (int m = 0; m < 4; m++) {
            int x = lane + 32 * m;
            s += kq[x] * d_G[i * D + x];
        }
        s = warp_sum(s);
        if (lane == 0) Hs[i] = s * SCL;
    }
    __syncthreads();

    // quad tables
    for (int e = tid; e < 6 * 256; e += 1024) {
        int q = e >> 8, idx = e & 255;
        Hq[e] = Hs[(4 * q + 0) * 4 + ((idx >> 6) & 3)]
              + Hs[(4 * q + 1) * 4 + ((idx >> 4) & 3)]
              + Hs[(4 * q + 2) * 4 + ((idx >> 2) & 3)]
              + Hs[(4 * q + 3) * 4 + (idx & 3)];
    }
    __syncthreads();

    // safe score upper bound (in scaled log2 units)
    if (warp < 6) {
        float m = -1e30f;
        #pragma unroll
        for (int r = 0; r < 8; r++) m = fmaxf(m, Hq[warp * 256 + lane + 32 * r]);
        #pragma unroll
        for (int o = 16; o; o >>= 1) m = fmaxf(m, __shfl_xor_sync(0xffffffffu, m, o));
        if (lane == 0) redf[warp] = m;
    } else if (warp == 6) {
        float m = (lane < 4) ? Hs[96 + lane] : -1e30f;
        #pragma unroll
        for (int o = 16; o; o >>= 1) m = fmaxf(m, __shfl_xor_sync(0xffffffffu, m, o));
        if (lane == 0) redf[6] = m;
    }
    __syncthreads();
    float bnd = redf[0] + redf[1] + redf[2] + redf[3] + redf[4] + redf[5] + redf[6];

    // scores -> exp weights + sum  (e = 2^(s - bnd), scale pre-folded)
    float lsum = 0.f;
    if (tid < 1018) {
        unsigned pw[6];
        #pragma unroll
        for (int q = 0; q < 6; q++) pw[q] = pat_u[tid + q];
        unsigned u6 = tok_u[tid + 6];
        const int l0 = tid * 4;
        #pragma unroll
        for (int k = 0; k < 4; k++) {
            float s = 0.f;
            #pragma unroll
            for (int q = 0; q < 6; q++)
                s += Hq[q * 256 + __byte_perm(pw[q], 0, 0x4440 + k)];
            s += Hs[96 + ((u6 >> (8 * k)) & 3)];
            float e = exp2f(s - bnd);
            sc[l0 + k] = e;
            lsum += e;
        }
    } else {
        int base = 4072 + (tid - 1018) * 4;
        sc[base + 0] = 0.f; sc[base + 1] = 0.f;
        sc[base + 2] = 0.f; sc[base + 3] = 0.f;
    }
    lsum = warp_sum(lsum);
    if (lane == 0) redf[warp] = lsum;
    __syncthreads();
    if (tid < 32) {
        float m = redf[tid];
        m = warp_sum(m);
        if (tid == 0) redf[34] = m;
    }
    __syncthreads();
    const float Z = redf[34];
    const float invZ = 1.0f / Z;

    // Phase 6: tap-grouped A. warp = group g (0..6) x slice s (0..3).
    const float4* sc4 = (const float4*)sc;
    if (warp < 28) {
        const int g = warp >> 2, s = warp & 3;
        float a00 = 0.f, a01 = 0.f, a02 = 0.f;
        float a10 = 0.f, a11 = 0.f, a12 = 0.f;
        float a20 = 0.f, a21 = 0.f, a22 = 0.f;
        float a30 = 0.f, a31 = 0.f, a32 = 0.f;
        #pragma unroll 2
        for (int it = 0; it < 8; it++) {
            const int lw = s * 256 + it * 32 + lane;
            float4 e4 = sc4[lw];
            unsigned u0 = tok_u[lw + g], u1 = tok_u[lw + g + 1];
            {
                unsigned tw = u0;
                int v0 = tw & 3, v1 = (tw >> 8) & 3, v2 = (tw >> 16) & 3, v3 = (tw >> 24) & 3;
                if (v0 == 0) a00 += e4.x; else if (v0 == 1) a01 += e4.x; else if (v0 == 2) a02 += e4.x;
                if (v1 == 0) a00 += e4.y; else if (v1 == 1) a01 += e4.y; else if (v1 == 2) a02 += e4.y;
                if (v2 == 0) a00 += e4.z; else if (v2 == 1) a01 += e4.z; else if (v2 == 2) a02 += e4.z;
                if (v3 == 0) a00 += e4.w; else if (v3 == 1) a01 += e4.w; else if (v3 == 2) a02 += e4.w;
            }
            if (g < 6) {
                {
                    unsigned tw = __funnelshift_r(u0, u1, 8);
                    int v0 = tw & 3, v1 = (tw >> 8) & 3, v2 = (tw >> 16) & 3, v3 = (tw >> 24) & 3;
                    if (v0 == 0) a10 += e4.x; else if (v0 == 1) a11 += e4.x; else if (v0 == 2) a12 += e4.x;
                    if (v1 == 0) a10 += e4.y; else if (v1 == 1) a11 += e4.y; else if (v1 == 2) a12 += e4.y;
                    if (v2 == 0) a10 += e4.z; else if (v2 == 1) a11 += e4.z; else if (v2 == 2) a12 += e4.z;
                    if (v3 == 0) a10 += e4.w; else if (v3 == 1) a11 += e4.w; else if (v3 == 2) a12 += e4.w;
                }
                {
                    unsigned tw = __funnelshift_r(u0, u1, 16);
                    int v0 = tw & 3, v1 = (tw >> 8) & 3, v2 = (tw >> 16) & 3, v3 = (tw >> 24) & 3;
                    if (v0 == 0) a20 += e4.x; else if (v0 == 1) a21 += e4.x; else if (v0 == 2) a22 += e4.x;
                    if (v1 == 0) a20 += e4.y; else if (v1 == 1) a21 += e4.y; else if (v1 == 2) a22 += e4.y;
                    if (v2 == 0) a20 += e4.z; else if (v2 == 1) a21 += e4.z; else if (v2 == 2) a22 += e4.z;
                    if (v3 == 0) a20 += e4.w; else if (v3 == 1) a21 += e4.w; else if (v3 == 2) a22 += e4.w;
                }
                {
                    unsigned tw = __funnelshift_r(u0, u1, 24);
                    int v0 = tw & 3, v1 = (tw >> 8) & 3, v2 = (tw >> 16) & 3, v3 = (tw >> 24) & 3;
                    if (v0 == 0) a30 += e4.x; else if (v0 == 1) a31 += e4.x; else if (v0 == 2) a32 += e4.x;
                    if (v1 == 0) a30 += e4.y; else if (v1 == 1) a31 += e4.y; else if (v1 == 2) a32 += e4.y;
                    if (v2 == 0) a30 += e4.z; else if (v2 == 1) a31 += e4.z; else if (v2 == 2) a32 += e4.z;
                    if (v3 == 0) a30 += e4.w; else if (v3 == 1) a31 += e4.w; else if (v3 == 2) a32 += e4.w;
                }
            }
        }
        a00 = warp_sum(a00); a01 = warp_sum(a01); a02 = warp_sum(a02);
        if (g < 6) {
            a10 = warp_sum(a10); a11 = warp_sum(a11); a12 = warp_sum(a12);
            a20 = warp_sum(a20); a21 = warp_sum(a21); a22 = warp_sum(a22);
            a30 = warp_sum(a30); a31 = warp_sum(a31); a32 = warp_sum(a32);
        }
        if (lane == 0) {
            float* p = &part[(g * 4 + s) * 12];
            p[0] = a00; p[1]  = a01; p[2]  = a02;
            p[3] = a10; p[4]  = a11; p[5]  = a12;
            p[6] = a20; p[7]  = a21; p[8]  = a22;
            p[9] = a30; p[10] = a31; p[11] = a32;
        }
    }
    __syncthreads();
    if (tid < T_EFF) {
        const int t = tid, g = t >> 2, r = t & 3;
        float s0 = 0.f, s1 = 0.f, s2 = 0.f;
        #pragma unroll
        for (int s_ = 0; s_ < 4; s_++) {
            const float* p = &part[(g * 4 + s_) * 12 + r * 3];
            s0 += p[0]; s1 += p[1]; s2 += p[2];
        }
        As[t * 4 + 0] = s0; As[t * 4 + 1] = s1;
        As[t * 4 + 2] = s2; As[t * 4 + 3] = Z - s0 - s1 - s2;
    }
    __syncthreads();

    // sv[x] = beff[x] + invZ * sum_i A_i * G[i][x]
    {
        int pt = tid >> 7, x = tid & 127;
        int i0 = pt * 13, i1 = (pt == 7) ? 100 : i0 + 13;
        float acc = 0.f;
        for (int i = i0; i < i1; i++) acc += As[i] * d_G[i * D + x];
        sc[pt * 128 + x] = acc;
    }
    __syncthreads();
    if (tid < D) {
        float acc = 0.f;
        #pragma unroll
        for (int p = 0; p < 8; p++) acc += sc[p * 128 + tid];
        sv[tid] = d_beff[tid] + acc * invZ;
    }
    __syncthreads();

    // out = Wv @ sv + bv
    for (int c = warp; c < D; c += 32) {
        float s = 0.f;
        #pragma unroll
        for (int m = 0; m < 4; m++) { int x = lane + 32 * m; s += wv[c * D + x] * sv[x]; }
        s = warp_sum(s);
        if (lane == 0) out[b * D + c] = s + bv[c];
    }
}

// ---------------------------------------------------------------------------
extern "C" void kernel_launch(void* const* d_in, const int* in_sizes, int n_in,
                              void* d_out, int out_size) {
    const int*   tokens = (const int*)  d_in[0];
    const float* emb    = (const float*)d_in[1];
    const float* w1     = (const float*)d_in[2];
    const float* b1     = (const float*)d_in[3];
    const float* wr     = (const float*)d_in[4];
    const float* br     = (const float*)d_in[5];
    const float* wq     = (const float*)d_in[6];
    const float* bq     = (const float*)d_in[7];
    const float* wk     = (const float*)d_in[8];
    const float* wv     = (const float*)d_in[10];
    const float* bv     = (const float*)d_in[11];

    const float* w2 = wr;
    const float* w3 = wr + D * D * KS;
    const float* b2 = br;
    const float* b3 = br + D;

    k_pre<<<GRID, 1024>>>(w1, emb, w2, b1, b2, w3, b3);
    k_main<<<BATCH, 1024>>>(tokens, wq, bq, wk, wv, bv, (float*)d_out);
}

// round 11
// speedup vs baseline: 1.0422x; 1.0422x over previous
#include <cuda_runtime.h>

#define D      128
#define KS     9
#define L_IN   4096
#define L_OUT  4072
#define T_EFF  25
#define T12    17
#define BATCH  128
#define ROW    (D * KS)   // 1152

// Inter-phase tables (transposed: channel contiguous -> coalesced reads)
__device__ float d_g1T[36 * D];        // [(v*9+k1)][c1]
__device__ float d_g2T[68 * D];        // [(v*17+t12)][c2]
__device__ float d_G  [100 * D];       // [(t*4+v)][c]
__device__ float d_bb2[D];
__device__ float d_beff[D];

__device__ __forceinline__ float warp_sum(float s) {
    #pragma unroll
    for (int o = 16; o; o >>= 1) s += __shfl_xor_sync(0xffffffffu, s, o);
    return s;
}

// ---------------------------------------------------------------------------
// pre1: c1 = bid. g1T[(v*9+k1)][c1] = sum_c0 W1[c1,c0,k1]*emb[v,c0]
__global__ __launch_bounds__(1024) void k_pre1(
    const float* __restrict__ w1, const float* __restrict__ emb)
{
    __shared__ float ws[ROW];
    __shared__ float es[4 * D];
    const int bid = blockIdx.x, tid = threadIdx.x;
    const int lane = tid & 31, warp = tid >> 5;
    const float* wrow = w1 + bid * ROW;
    for (int i = tid; i < ROW; i += 1024) ws[i] = wrow[i];
    if (tid < 512) es[tid] = emb[tid];
    __syncthreads();
    for (int pr = warp; pr < 36; pr += 32) {
        const int v = pr / KS, k1 = pr % KS;
        float s = 0.f;
        #pragma unroll
        for (int m = 0; m < 4; m++) {
            int c0 = lane + 32 * m;
            s += ws[c0 * KS + k1] * es[v * D + c0];
        }
        s = warp_sum(s);
        if (lane == 0) d_g1T[pr * D + bid] = s;
    }
}

// ---------------------------------------------------------------------------
// pre2: c2 = bid. g2T + bb2.
__global__ __launch_bounds__(1024) void k_pre2(
    const float* __restrict__ w2, const float* __restrict__ b1,
    const float* __restrict__ b2)
{
    __shared__ float ws[ROW];
    const int bid = blockIdx.x, tid = threadIdx.x;
    const int lane = tid & 31, warp = tid >> 5;
    const float* wrow = w2 + bid * ROW;
    for (int i = tid; i < ROW; i += 1024) ws[i] = wrow[i];
    __syncthreads();
    for (int pr = warp; pr < 69; pr += 32) {
        if (pr < 68) {
            const int v = pr / T12, t = pr % T12;
            const int klo = (t > KS - 1) ? t - (KS - 1) : 0;
            const int khi = (t < KS - 1) ? t : KS - 1;
            float s = 0.f;
            for (int k2 = klo; k2 <= khi; k2++) {
                const int k1 = t - k2;
                const float* g1r = d_g1T + (v * KS + k1) * D;
                #pragma unroll
                for (int m = 0; m < 4; m++) {
                    int c1 = lane + 32 * m;
                    s += ws[c1 * KS + k2] * g1r[c1];
                }
            }
            s = warp_sum(s);
            if (lane == 0) d_g2T[(v * T12 + t) * D + bid] = s;
        } else {
            float s = 0.f;
            #pragma unroll 4
            for (int i = 0; i < 36; i++) {
                int idx = lane + 32 * i;
                s += ws[idx] * b1[idx / KS];
            }
            s = warp_sum(s);
            if (lane == 0) d_bb2[bid] = b2[bid] + s;
        }
    }
}

// ---------------------------------------------------------------------------
// pre3: c3 = bid. G + beff.
__global__ __launch_bounds__(1024) void k_pre3(
    const float* __restrict__ w3, const float* __restrict__ b3)
{
    __shared__ float ws[ROW];
    const int bid = blockIdx.x, tid = threadIdx.x;
    const int lane = tid & 31, warp = tid >> 5;
    const float* wrow = w3 + bid * ROW;
    for (int i = tid; i < ROW; i += 1024) ws[i] = wrow[i];
    __syncthreads();
    for (int pr = warp; pr < 101; pr += 32) {
        if (pr < 100) {
            const int v = pr & 3, t = pr >> 2;
            const int klo = (t > T12 - 1) ? t - (T12 - 1) : 0;
            const int khi = (t < KS - 1) ? t : KS - 1;
            float s = 0.f;
            for (int k3 = klo; k3 <= khi; k3++) {
                const int t12 = t - k3;
                const float* g2r = d_g2T + (v * T12 + t12) * D;
                #pragma unroll
                for (int m = 0; m < 4; m++) {
                    int c2 = lane + 32 * m;
                    s += ws[c2 * KS + k3] * g2r[c2];
                }
            }
            s = warp_sum(s);
            if (lane == 0) d_G[(t * 4 + v) * D + bid] = s;
        } else {
            float s = 0.f;
            #pragma unroll 4
            for (int i = 0; i < 36; i++) {
                int idx = lane + 32 * i;
                s += ws[idx] * d_bb2[idx / KS];
            }
            s = warp_sum(s);
            if (lane == 0) d_beff[bid] = b3[bid] + s;
        }
    }
}

// ---------------------------------------------------------------------------
// Main kernel: one CTA per batch row.
__global__ __launch_bounds__(1024) void k_main(
    const int*   __restrict__ tokens,
    const float* __restrict__ wq, const float* __restrict__ bq,
    const float* __restrict__ wk,
    const float* __restrict__ wv, const float* __restrict__ bv,
    float* __restrict__ out)
{
    __shared__ __align__(16) float sc[4096];
    __shared__ float Hq[6 * 256];
    __shared__ float Hs[128];
    __shared__ float As[128];
    __shared__ float cntf[128];
    __shared__ float rm[128];
    __shared__ float qv[128];
    __shared__ float kq[128];
    __shared__ float sv[128];
    __shared__ float part[7 * 4 * 12];
    __shared__ float redf[40];
    __shared__ int   cnti[4];
    __shared__ unsigned tok_u[1032];
    __shared__ unsigned pat_u[1032];
    unsigned char* tok = (unsigned char*)tok_u;

    const int b = blockIdx.x, tid = threadIdx.x;
    const int lane = tid & 31, warp = tid >> 5;

    // scores scale folded into Hs: SCL = (1/sqrt(128)) * log2(e)
    const float SCL = 0.088388347648318447f * 1.4426950408889634f;

    // tokens -> packed bytes
    {
        const int4* tb4 = (const int4*)(tokens + b * L_IN);
        int4 w = tb4[tid];
        tok_u[tid] = (unsigned)w.x | ((unsigned)w.y << 8) |
                     ((unsigned)w.z << 16) | ((unsigned)w.w << 24);
    }
    if (tid < 8) tok_u[1024 + tid] = 0;
    if (tid < 4) cnti[tid] = 0;
    __syncthreads();

    // quad patterns
    for (int i = tid; i < 1030; i += 1024) {
        unsigned w0 = tok_u[i], w1w = tok_u[i + 1];
        unsigned p0 = ((w0 & 0x03030303u) * 0x40100401u) >> 24;
        unsigned f1 = __funnelshift_r(w0, w1w, 8);
        unsigned p1 = ((f1 & 0x03030303u) * 0x40100401u) >> 24;
        unsigned f2 = __funnelshift_r(w0, w1w, 16);
        unsigned p2 = ((f2 & 0x03030303u) * 0x40100401u) >> 24;
        unsigned f3 = __funnelshift_r(w0, w1w, 24);
        unsigned p3 = ((f3 & 0x03030303u) * 0x40100401u) >> 24;
        pat_u[i] = p0 | (p1 << 8) | (p2 << 16) | (p3 << 24);
    }

    // full counts
    {
        unsigned u = tok_u[tid];
        int l0 = 0, l1 = 0, l2 = 0, l3 = 0;
        #pragma unroll
        for (int j = 0; j < 4; j++) {
            int v = (u >> (8 * j)) & 3;
            l0 += (v == 0); l1 += (v == 1); l2 += (v == 2); l3 += (v == 3);
        }
        #pragma unroll
        for (int o = 16; o; o >>= 1) {
            l0 += __shfl_xor_sync(0xffffffffu, l0, o);
            l1 += __shfl_xor_sync(0xffffffffu, l1, o);
            l2 += __shfl_xor_sync(0xffffffffu, l2, o);
            l3 += __shfl_xor_sync(0xffffffffu, l3, o);
        }
        if (lane == 0) {
            atomicAdd(&cnti[0], l0); atomicAdd(&cnti[1], l1);
            atomicAdd(&cnti[2], l2); atomicAdd(&cnti[3], l3);
        }
    }
    __syncthreads();

    // windowed counts
    if (warp == 0 && lane < T_EFF) {
        int t = lane;
        int c0 = cnti[0], c1 = cnti[1], c2 = cnti[2], c3 = cnti[3];
        for (int j = 0; j < t; j++) {
            int v = tok[j];
            c0 -= (v == 0); c1 -= (v == 1); c2 -= (v == 2); c3 -= (v == 3);
        }
        for (int j = t + L_OUT; j < L_IN; j++) {
            int v = tok[j];
            c0 -= (v == 0); c1 -= (v == 1); c2 -= (v == 2); c3 -= (v == 3);
        }
        cntf[t * 4 + 0] = (float)c0; cntf[t * 4 + 1] = (float)c1;
        cntf[t * 4 + 2] = (float)c2; cntf[t * 4 + 3] = (float)c3;
    }
    __syncthreads();

    // rm[x] = beff[x] + (1/L) * sum_i cnt_i * G[i][x]
    {
        int pt = tid >> 7, x = tid & 127;
        int i0 = pt * 13, i1 = (pt == 7) ? 100 : i0 + 13;
        float acc = 0.f;
        for (int i = i0; i < i1; i++) acc += cntf[i] * d_G[i * D + x];
        sc[pt * 128 + x] = acc;
    }
    __syncthreads();
    if (tid < D) {
        float acc = 0.f;
        #pragma unroll
        for (int p = 0; p < 8; p++) acc += sc[p * 128 + tid];
        rm[tid] = d_beff[tid] + acc * (1.0f / (float)L_OUT);
    }
    __syncthreads();

    // q = Wq @ rm + bq
    for (int c = warp; c < D; c += 32) {
        float s = 0.f;
        #pragma unroll
        for (int m = 0; m < 4; m++) { int x = lane + 32 * m; s += wq[c * D + x] * rm[x]; }
        s = warp_sum(s);
        if (lane == 0) qv[c] = s + bq[c];
    }
    __syncthreads();

    // kq[x] = sum_c Wk[c][x] * q[c]
    {
        int g = tid >> 7, x = tid & 127;
        float s = 0.f;
        #pragma unroll
        for (int o = 0; o < 16; o++) s += wk[(g * 16 + o) * D + x] * qv[g * 16 + o];
        sc[g * D + x] = s;
    }
    __syncthreads();
    if (tid < D) {
        float s = 0.f;
        #pragma unroll
        for (int g = 0; g < 8; g++) s += sc[g * D + tid];
        kq[tid] = s;
    }
    __syncthreads();

    // Hs[i] = SCL * (G[i,:] . kq)   -- scale folded in (log2 units)
    for (int i = warp; i < 100; i += 32) {
        float s = 0.f;
        #pragma unroll
        for (int m = 0; m < 4; m++) {
            int x = lane + 32 * m;
            s += kq[x] * d_G[i * D + x];
        }
        s = warp_sum(s);
        if (lane == 0) Hs[i] = s * SCL;
    }
    __syncthreads();

    // quad tables (log2 units)
    for (int e = tid; e < 6 * 256; e += 1024) {
        int q = e >> 8, idx = e & 255;
        Hq[e] = Hs[(4 * q + 0) * 4 + ((idx >> 6) & 3)]
              + Hs[(4 * q + 1) * 4 + ((idx >> 4) & 3)]
              + Hs[(4 * q + 2) * 4 + ((idx >> 2) & 3)]
              + Hs[(4 * q + 3) * 4 + (idx & 3)];
    }
    __syncthreads();

    // per-table maxima
    if (warp < 6) {
        float m = -1e30f;
        #pragma unroll
        for (int r = 0; r < 8; r++) m = fmaxf(m, Hq[warp * 256 + lane + 32 * r]);
        #pragma unroll
        for (int o = 16; o; o >>= 1) m = fmaxf(m, __shfl_xor_sync(0xffffffffu, m, o));
        if (lane == 0) redf[warp] = m;
    } else if (warp == 6) {
        float m = (lane < 4) ? Hs[96 + lane] : -1e30f;
        #pragma unroll
        for (int o = 16; o; o >>= 1) m = fmaxf(m, __shfl_xor_sync(0xffffffffu, m, o));
        if (lane == 0) redf[6] = m;
    }
    __syncthreads();

    // Exponentiate the tables in place: Hq[e] <- 2^(Hq[e]-max_q), Hs6 likewise.
    // Then each score weight is a product of 7 factors, each <= 1.
    for (int e = tid; e < 6 * 256; e += 1024)
        Hq[e] = exp2f(Hq[e] - redf[e >> 8]);
    if (tid < 4)
        Hs[96 + tid] = exp2f(Hs[96 + tid] - redf[6]);
    __syncthreads();

    // scores -> exp weights + sum  (pure products, no MUFU)
    float lsum = 0.f;
    if (tid < 1018) {
        unsigned pw[6];
        #pragma unroll
        for (int q = 0; q < 6; q++) pw[q] = pat_u[tid + q];
        unsigned u6 = tok_u[tid + 6];
        const int l0 = tid * 4;
        #pragma unroll
        for (int k = 0; k < 4; k++) {
            float e = Hq[0 * 256 + __byte_perm(pw[0], 0, 0x4440 + k)];
            e *= Hq[1 * 256 + __byte_perm(pw[1], 0, 0x4440 + k)];
            e *= Hq[2 * 256 + __byte_perm(pw[2], 0, 0x4440 + k)];
            e *= Hq[3 * 256 + __byte_perm(pw[3], 0, 0x4440 + k)];
            e *= Hq[4 * 256 + __byte_perm(pw[4], 0, 0x4440 + k)];
            e *= Hq[5 * 256 + __byte_perm(pw[5], 0, 0x4440 + k)];
            e *= Hs[96 + ((u6 >> (8 * k)) & 3)];
            sc[l0 + k] = e;
            lsum += e;
        }
    } else {
        int base = 4072 + (tid - 1018) * 4;
        sc[base + 0] = 0.f; sc[base + 1] = 0.f;
        sc[base + 2] = 0.f; sc[base + 3] = 0.f;
    }
    lsum = warp_sum(lsum);
    if (lane == 0) redf[warp] = lsum;
    __syncthreads();
    if (tid < 32) {
        float m = redf[tid];
        m = warp_sum(m);
        if (tid == 0) redf[34] = m;
    }
    __syncthreads();
    const float Z = redf[34];
    const float invZ = 1.0f / Z;

    // Phase 6: tap-grouped A. warp = group g (0..6) x slice s (0..3).
    const float4* sc4 = (const float4*)sc;
    if (warp < 28) {
        const int g = warp >> 2, s = warp & 3;
        float a00 = 0.f, a01 = 0.f, a02 = 0.f;
        float a10 = 0.f, a11 = 0.f, a12 = 0.f;
        float a20 = 0.f, a21 = 0.f, a22 = 0.f;
        float a30 = 0.f, a31 = 0.f, a32 = 0.f;
        #pragma unroll 2
        for (int it = 0; it < 8; it++) {
            const int lw = s * 256 + it * 32 + lane;
            float4 e4 = sc4[lw];
            unsigned u0 = tok_u[lw + g], u1 = tok_u[lw + g + 1];
            {
                unsigned tw = u0;
                int v0 = tw & 3, v1 = (tw >> 8) & 3, v2 = (tw >> 16) & 3, v3 = (tw >> 24) & 3;
                if (v0 == 0) a00 += e4.x; else if (v0 == 1) a01 += e4.x; else if (v0 == 2) a02 += e4.x;
                if (v1 == 0) a00 += e4.y; else if (v1 == 1) a01 += e4.y; else if (v1 == 2) a02 += e4.y;
                if (v2 == 0) a00 += e4.z; else if (v2 == 1) a01 += e4.z; else if (v2 == 2) a02 += e4.z;
                if (v3 == 0) a00 += e4.w; else if (v3 == 1) a01 += e4.w; else if (v3 == 2) a02 += e4.w;
            }
            if (g < 6) {
                {
                    unsigned tw = __funnelshift_r(u0, u1, 8);
                    int v0 = tw & 3, v1 = (tw >> 8) & 3, v2 = (tw >> 16) & 3, v3 = (tw >> 24) & 3;
                    if (v0 == 0) a10 += e4.x; else if (v0 == 1) a11 += e4.x; else if (v0 == 2) a12 += e4.x;
                    if (v1 == 0) a10 += e4.y; else if (v1 == 1) a11 += e4.y; else if (v1 == 2) a12 += e4.y;
                    if (v2 == 0) a10 += e4.z; else if (v2 == 1) a11 += e4.z; else if (v2 == 2) a12 += e4.z;
                    if (v3 == 0) a10 += e4.w; else if (v3 == 1) a11 += e4.w; else if (v3 == 2) a12 += e4.w;
                }
                {
                    unsigned tw = __funnelshift_r(u0, u1, 16);
                    int v0 = tw & 3, v1 = (tw >> 8) & 3, v2 = (tw >> 16) & 3, v3 = (tw >> 24) & 3;
                    if (v0 == 0) a20 += e4.x; else if (v0 == 1) a21 += e4.x; else if (v0 == 2) a22 += e4.x;
                    if (v1 == 0) a20 += e4.y; else if (v1 == 1) a21 += e4.y; else if (v1 == 2) a22 += e4.y;
                    if (v2 == 0) a20 += e4.z; else if (v2 == 1) a21 += e4.z; else if (v2 == 2) a22 += e4.z;
                    if (v3 == 0) a20 += e4.w; else if (v3 == 1) a21 += e4.w; else if (v3 == 2) a22 += e4.w;
                }
                {
                    unsigned tw = __funnelshift_r(u0, u1, 24);
                    int v0 = tw & 3, v1 = (tw >> 8) & 3, v2 = (tw >> 16) & 3, v3 = (tw >> 24) & 3;
                    if (v0 == 0) a30 += e4.x; else if (v0 == 1) a31 += e4.x; else if (v0 == 2) a32 += e4.x;
                    if (v1 == 0) a30 += e4.y; else if (v1 == 1) a31 += e4.y; else if (v1 == 2) a32 += e4.y;
                    if (v2 == 0) a30 += e4.z; else if (v2 == 1) a31 += e4.z; else if (v2 == 2) a32 += e4.z;
                    if (v3 == 0) a30 += e4.w; else if (v3 == 1) a31 += e4.w; else if (v3 == 2) a32 += e4.w;
                }
            }
        }
        a00 = warp_sum(a00); a01 = warp_sum(a01); a02 = warp_sum(a02);
        if (g < 6) {
            a10 = warp_sum(a10); a11 = warp_sum(a11); a12 = warp_sum(a12);
            a20 = warp_sum(a20); a21 = warp_sum(a21); a22 = warp_sum(a22);
            a30 = warp_sum(a30); a31 = warp_sum(a31); a32 = warp_sum(a32);
        }
        if (lane == 0) {
            float* p = &part[(g * 4 + s) * 12];
            p[0] = a00; p[1]  = a01; p[2]  = a02;
            p[3] = a10; p[4]  = a11; p[5]  = a12;
            p[6] = a20; p[7]  = a21; p[8]  = a22;
            p[9] = a30; p[10] = a31; p[11] = a32;
        }
    }
    __syncthreads();
    if (tid < T_EFF) {
        const int t = tid, g = t >> 2, r = t & 3;
        float s0 = 0.f, s1 = 0.f, s2 = 0.f;
        #pragma unroll
        for (int s_ = 0; s_ < 4; s_++) {
            const float* p = &part[(g * 4 + s_) * 12 + r * 3];
            s0 += p[0]; s1 += p[1]; s2 += p[2];
        }
        As[t * 4 + 0] = s0; As[t * 4 + 1] = s1;
        As[t * 4 + 2] = s2; As[t * 4 + 3] = Z - s0 - s1 - s2;
    }
    __syncthreads();

    // sv[x] = beff[x] + invZ * sum_i A_i * G[i][x]
    {
        int pt = tid >> 7, x = tid & 127;
        int i0 = pt * 13, i1 = (pt == 7) ? 100 : i0 + 13;
        float acc = 0.f;
        for (int i = i0; i < i1; i++) acc += As[i] * d_G[i * D + x];
        sc[pt * 128 + x] = acc;
    }
    __syncthreads();
    if (tid < D) {
        float acc = 0.f;
        #pragma unroll
        for (int p = 0; p < 8; p++) acc += sc[p * 128 + tid];
        sv[tid] = d_beff[tid] + acc * invZ;
    }
    __syncthreads();

    // out = Wv @ sv + bv
    for (int c = warp; c < D; c += 32) {
        float s = 0.f;
        #pragma unroll
        for (int m = 0; m < 4; m++) { int x = lane + 32 * m; s += wv[c * D + x] * sv[x]; }
        s = warp_sum(s);
        if (lane == 0) out[b * D + c] = s + bv[c];
    }
}

// ---------------------------------------------------------------------------
extern "C" void kernel_launch(void* const* d_in, const int* in_sizes, int n_in,
                              void* d_out, int out_size) {
    const int*   tokens = (const int*)  d_in[0];
    const float* emb    = (const float*)d_in[1];
    const float* w1     = (const float*)d_in[2];
    const float* b1     = (const float*)d_in[3];
    const float* wr     = (const float*)d_in[4];
    const float* br     = (const float*)d_in[5];
    const float* wq     = (const float*)d_in[6];
    const float* bq     = (const float*)d_in[7];
    const float* wk     = (const float*)d_in[8];
    const float* wv     = (const float*)d_in[10];
    const float* bv     = (const float*)d_in[11];

    const float* w2 = wr;
    const float* w3 = wr + D * D * KS;
    const float* b2 = br;
    const float* b3 = br + D;

    k_pre1<<<128, 1024>>>(w1, emb);
    k_pre2<<<128, 1024>>>(w2, b1, b2);
    k_pre3<<<128, 1024>>>(w3, b3);
    k_main<<<BATCH, 1024>>>(tokens, wq, bq, wk, wv, bv, (float*)d_out);
}

// round 12
// speedup vs baseline: 1.0735x; 1.0300x over previous
#include <cuda_runtime.h>

#define D      128
#define KS     9
#define L_IN   4096
#define L_OUT  4072
#define T_EFF  25
#define T12    17
#define BATCH  128
#define ROW    (D * KS)   // 1152

// Inter-phase tables (transposed: channel contiguous -> coalesced reads)
__device__ float d_g1T[36 * D];        // [(v*9+k1)][c1]
__device__ float d_g2T[68 * D];        // [(v*17+t12)][c2]
__device__ float d_G  [100 * D];       // [(t*4+v)][c]
__device__ float d_bb2[D];
__device__ float d_beff[D];

__device__ __forceinline__ float warp_sum(float s) {
    #pragma unroll
    for (int o = 16; o; o >>= 1) s += __shfl_xor_sync(0xffffffffu, s, o);
    return s;
}

// ---------------------------------------------------------------------------
// pre1: c1 = bid. g1T[(v*9+k1)][c1] = sum_c0 W1[c1,c0,k1]*emb[v,c0]
__global__ __launch_bounds__(1024) void k_pre1(
    const float* __restrict__ w1, const float* __restrict__ emb)
{
    __shared__ float ws[ROW];
    __shared__ float es[4 * D];
    const int bid = blockIdx.x, tid = threadIdx.x;
    const int lane = tid & 31, warp = tid >> 5;
    const float* wrow = w1 + bid * ROW;
    for (int i = tid; i < ROW; i += 1024) ws[i] = wrow[i];
    if (tid < 512) es[tid] = emb[tid];
    __syncthreads();
    for (int pr = warp; pr < 36; pr += 32) {
        const int v = pr / KS, k1 = pr % KS;
        float s = 0.f;
        #pragma unroll
        for (int m = 0; m < 4; m++) {
            int c0 = lane + 32 * m;
            s += ws[c0 * KS + k1] * es[v * D + c0];
        }
        s = warp_sum(s);
        if (lane == 0) d_g1T[pr * D + bid] = s;
    }
}

// ---------------------------------------------------------------------------
// pre2: c2 = bid. g2T + bb2.
__global__ __launch_bounds__(1024) void k_pre2(
    const float* __restrict__ w2, const float* __restrict__ b1,
    const float* __restrict__ b2)
{
    __shared__ float ws[ROW];
    const int bid = blockIdx.x, tid = threadIdx.x;
    const int lane = tid & 31, warp = tid >> 5;
    const float* wrow = w2 + bid * ROW;
    for (int i = tid; i < ROW; i += 1024) ws[i] = wrow[i];
    __syncthreads();
    for (int pr = warp; pr < 69; pr += 32) {
        if (pr < 68) {
            const int v = pr / T12, t = pr % T12;
            const int klo = (t > KS - 1) ? t - (KS - 1) : 0;
            const int khi = (t < KS - 1) ? t : KS - 1;
            float s = 0.f;
            for (int k2 = klo; k2 <= khi; k2++) {
                const int k1 = t - k2;
                const float* g1r = d_g1T + (v * KS + k1) * D;
                #pragma unroll
                for (int m = 0; m < 4; m++) {
                    int c1 = lane + 32 * m;
                    s += ws[c1 * KS + k2] * g1r[c1];
                }
            }
            s = warp_sum(s);
            if (lane == 0) d_g2T[(v * T12 + t) * D + bid] = s;
        } else {
            float s = 0.f;
            #pragma unroll 4
            for (int i = 0; i < 36; i++) {
                int idx = lane + 32 * i;
                s += ws[idx] * b1[idx / KS];
            }
            s = warp_sum(s);
            if (lane == 0) d_bb2[bid] = b2[bid] + s;
        }
    }
}

// ---------------------------------------------------------------------------
// pre3: c3 = bid. G + beff.
__global__ __launch_bounds__(1024) void k_pre3(
    const float* __restrict__ w3, const float* __restrict__ b3)
{
    __shared__ float ws[ROW];
    const int bid = blockIdx.x, tid = threadIdx.x;
    const int lane = tid & 31, warp = tid >> 5;
    const float* wrow = w3 + bid * ROW;
    for (int i = tid; i < ROW; i += 1024) ws[i] = wrow[i];
    __syncthreads();
    for (int pr = warp; pr < 101; pr += 32) {
        if (pr < 100) {
            const int v = pr & 3, t = pr >> 2;
            const int klo = (t > T12 - 1) ? t - (T12 - 1) : 0;
            const int khi = (t < KS - 1) ? t : KS - 1;
            float s = 0.f;
            for (int k3 = klo; k3 <= khi; k3++) {
                const int t12 = t - k3;
                const float* g2r = d_g2T + (v * T12 + t12) * D;
                #pragma unroll
                for (int m = 0; m < 4; m++) {
                    int c2 = lane + 32 * m;
                    s += ws[c2 * KS + k3] * g2r[c2];
                }
            }
            s = warp_sum(s);
            if (lane == 0) d_G[(t * 4 + v) * D + bid] = s;
        } else {
            float s = 0.f;
            #pragma unroll 4
            for (int i = 0; i < 36; i++) {
                int idx = lane + 32 * i;
                s += ws[idx] * d_bb2[idx / KS];
            }
            s = warp_sum(s);
            if (lane == 0) d_beff[bid] = b3[bid] + s;
        }
    }
}

// ---------------------------------------------------------------------------
// Main kernel: one CTA per batch row.
__global__ __launch_bounds__(1024) void k_main(
    const int*   __restrict__ tokens,
    const float* __restrict__ wq, const float* __restrict__ bq,
    const float* __restrict__ wk,
    const float* __restrict__ wv, const float* __restrict__ bv,
    float* __restrict__ out)
{
    __shared__ __align__(16) float sc[4096];
    __shared__ float Hq[6 * 256];
    __shared__ float Hs[128];
    __shared__ float As[128];
    __shared__ float cntf[128];
    __shared__ float rm[128];
    __shared__ float qv[128];
    __shared__ float kq[128];
    __shared__ float sv[128];
    __shared__ float part[7 * 4 * 12];
    __shared__ float redf[40];
    __shared__ int   cnti[4];
    __shared__ unsigned tok_u[1032];
    __shared__ unsigned pat_u[1032];
    unsigned char* tok = (unsigned char*)tok_u;

    const int b = blockIdx.x, tid = threadIdx.x;
    const int lane = tid & 31, warp = tid >> 5;

    // scores scale folded into Hs: SCL = (1/sqrt(128)) * log2(e)
    const float SCL = 0.088388347648318447f * 1.4426950408889634f;

    // tokens -> packed bytes
    {
        const int4* tb4 = (const int4*)(tokens + b * L_IN);
        int4 w = tb4[tid];
        tok_u[tid] = (unsigned)w.x | ((unsigned)w.y << 8) |
                     ((unsigned)w.z << 16) | ((unsigned)w.w << 24);
    }
    if (tid < 8) tok_u[1024 + tid] = 0;
    if (tid < 4) cnti[tid] = 0;
    __syncthreads();

    // quad patterns
    for (int i = tid; i < 1030; i += 1024) {
        unsigned w0 = tok_u[i], w1w = tok_u[i + 1];
        unsigned p0 = ((w0 & 0x03030303u) * 0x40100401u) >> 24;
        unsigned f1 = __funnelshift_r(w0, w1w, 8);
        unsigned p1 = ((f1 & 0x03030303u) * 0x40100401u) >> 24;
        unsigned f2 = __funnelshift_r(w0, w1w, 16);
        unsigned p2 = ((f2 & 0x03030303u) * 0x40100401u) >> 24;
        unsigned f3 = __funnelshift_r(w0, w1w, 24);
        unsigned p3 = ((f3 & 0x03030303u) * 0x40100401u) >> 24;
        pat_u[i] = p0 | (p1 << 8) | (p2 << 16) | (p3 << 24);
    }

    // full counts
    {
        unsigned u = tok_u[tid];
        int l0 = 0, l1 = 0, l2 = 0, l3 = 0;
        #pragma unroll
        for (int j = 0; j < 4; j++) {
            int v = (u >> (8 * j)) & 3;
            l0 += (v == 0); l1 += (v == 1); l2 += (v == 2); l3 += (v == 3);
        }
        #pragma unroll
        for (int o = 16; o; o >>= 1) {
            l0 += __shfl_xor_sync(0xffffffffu, l0, o);
            l1 += __shfl_xor_sync(0xffffffffu, l1, o);
            l2 += __shfl_xor_sync(0xffffffffu, l2, o);
            l3 += __shfl_xor_sync(0xffffffffu, l3, o);
        }
        if (lane == 0) {
            atomicAdd(&cnti[0], l0); atomicAdd(&cnti[1], l1);
            atomicAdd(&cnti[2], l2); atomicAdd(&cnti[3], l3);
        }
    }
    __syncthreads();

    // windowed counts
    if (warp == 0 && lane < T_EFF) {
        int t = lane;
        int c0 = cnti[0], c1 = cnti[1], c2 = cnti[2], c3 = cnti[3];
        for (int j = 0; j < t; j++) {
            int v = tok[j];
            c0 -= (v == 0); c1 -= (v == 1); c2 -= (v == 2); c3 -= (v == 3);
        }
        for (int j = t + L_OUT; j < L_IN; j++) {
            int v = tok[j];
            c0 -= (v == 0); c1 -= (v == 1); c2 -= (v == 2); c3 -= (v == 3);
        }
        cntf[t * 4 + 0] = (float)c0; cntf[t * 4 + 1] = (float)c1;
        cntf[t * 4 + 2] = (float)c2; cntf[t * 4 + 3] = (float)c3;
    }
    __syncthreads();

    // rm[x] = beff[x] + (1/L) * sum_i cnt_i * G[i][x]
    {
        int pt = tid >> 7, x = tid & 127;
        int i0 = pt * 13, i1 = (pt == 7) ? 100 : i0 + 13;
        float acc = 0.f;
        for (int i = i0; i < i1; i++) acc += cntf[i] * d_G[i * D + x];
        sc[pt * 128 + x] = acc;
    }
    __syncthreads();
    if (tid < D) {
        float acc = 0.f;
        #pragma unroll
        for (int p = 0; p < 8; p++) acc += sc[p * 128 + tid];
        rm[tid] = d_beff[tid] + acc * (1.0f / (float)L_OUT);
    }
    __syncthreads();

    // q = Wq @ rm + bq
    for (int c = warp; c < D; c += 32) {
        float s = 0.f;
        #pragma unroll
        for (int m = 0; m < 4; m++) { int x = lane + 32 * m; s += wq[c * D + x] * rm[x]; }
        s = warp_sum(s);
        if (lane == 0) qv[c] = s + bq[c];
    }
    __syncthreads();

    // kq[x] = sum_c Wk[c][x] * q[c]
    {
        int g = tid >> 7, x = tid & 127;
        float s = 0.f;
        #pragma unroll
        for (int o = 0; o < 16; o++) s += wk[(g * 16 + o) * D + x] * qv[g * 16 + o];
        sc[g * D + x] = s;
    }
    __syncthreads();
    if (tid < D) {
        float s = 0.f;
        #pragma unroll
        for (int g = 0; g < 8; g++) s += sc[g * D + tid];
        kq[tid] = s;
    }
    __syncthreads();

    // Hs[i] = SCL * (G[i,:] . kq)   (log2 units)
    for (int i = warp; i < 100; i += 32) {
        float s = 0.f;
        #pragma unroll
        for (int m = 0; m < 4; m++) {
            int x = lane + 32 * m;
            s += kq[x] * d_G[i * D + x];
        }
        s = warp_sum(s);
        if (lane == 0) Hs[i] = s * SCL;
    }
    __syncthreads();

    // quad tables (log2 units)
    for (int e = tid; e < 6 * 256; e += 1024) {
        int q = e >> 8, idx = e & 255;
        Hq[e] = Hs[(4 * q + 0) * 4 + ((idx >> 6) & 3)]
              + Hs[(4 * q + 1) * 4 + ((idx >> 4) & 3)]
              + Hs[(4 * q + 2) * 4 + ((idx >> 2) & 3)]
              + Hs[(4 * q + 3) * 4 + (idx & 3)];
    }
    __syncthreads();

    // per-table maxima
    if (warp < 6) {
        float m = -1e30f;
        #pragma unroll
        for (int r = 0; r < 8; r++) m = fmaxf(m, Hq[warp * 256 + lane + 32 * r]);
        #pragma unroll
        for (int o = 16; o; o >>= 1) m = fmaxf(m, __shfl_xor_sync(0xffffffffu, m, o));
        if (lane == 0) redf[warp] = m;
    } else if (warp == 6) {
        float m = (lane < 4) ? Hs[96 + lane] : -1e30f;
        #pragma unroll
        for (int o = 16; o; o >>= 1) m = fmaxf(m, __shfl_xor_sync(0xffffffffu, m, o));
        if (lane == 0) redf[6] = m;
    }
    __syncthreads();

    // Exponentiate the tables in place.
    for (int e = tid; e < 6 * 256; e += 1024)
        Hq[e] = exp2f(Hq[e] - redf[e >> 8]);
    if (tid < 4)
        Hs[96 + tid] = exp2f(Hs[96 + tid] - redf[6]);
    __syncthreads();

    // scores -> exp weights + sum  (pure products)
    float lsum = 0.f;
    if (tid < 1018) {
        unsigned pw[6];
        #pragma unroll
        for (int q = 0; q < 6; q++) pw[q] = pat_u[tid + q];
        unsigned u6 = tok_u[tid + 6];
        const int l0 = tid * 4;
        #pragma unroll
        for (int k = 0; k < 4; k++) {
            float e = Hq[0 * 256 + __byte_perm(pw[0], 0, 0x4440 + k)];
            e *= Hq[1 * 256 + __byte_perm(pw[1], 0, 0x4440 + k)];
            e *= Hq[2 * 256 + __byte_perm(pw[2], 0, 0x4440 + k)];
            e *= Hq[3 * 256 + __byte_perm(pw[3], 0, 0x4440 + k)];
            e *= Hq[4 * 256 + __byte_perm(pw[4], 0, 0x4440 + k)];
            e *= Hq[5 * 256 + __byte_perm(pw[5], 0, 0x4440 + k)];
            e *= Hs[96 + ((u6 >> (8 * k)) & 3)];
            sc[l0 + k] = e;
            lsum += e;
        }
    } else {
        int base = 4072 + (tid - 1018) * 4;
        sc[base + 0] = 0.f; sc[base + 1] = 0.f;
        sc[base + 2] = 0.f; sc[base + 3] = 0.f;
    }
    lsum = warp_sum(lsum);
    if (lane == 0) redf[warp] = lsum;
    __syncthreads();
    if (tid < 32) {
        float m = redf[tid];
        m = warp_sum(m);
        if (tid == 0) redf[34] = m;
    }
    __syncthreads();
    const float Z = redf[34];
    const float invZ = 1.0f / Z;

    // Phase 6: tap-grouped A — BRANCHLESS selects (no BSSY/BSYNC).
    const float4* sc4 = (const float4*)sc;
    if (warp < 28) {
        const int g = warp >> 2, s = warp & 3;
        float a00 = 0.f, a01 = 0.f, a02 = 0.f;
        float a10 = 0.f, a11 = 0.f, a12 = 0.f;
        float a20 = 0.f, a21 = 0.f, a22 = 0.f;
        float a30 = 0.f, a31 = 0.f, a32 = 0.f;
        #pragma unroll 2
        for (int it = 0; it < 8; it++) {
            const int lw = s * 256 + it * 32 + lane;
            float4 e4 = sc4[lw];
            unsigned u0 = tok_u[lw + g], u1 = tok_u[lw + g + 1];
            {
                unsigned tw = u0;
                int v0 = tw & 3, v1 = (tw >> 8) & 3, v2 = (tw >> 16) & 3, v3 = (tw >> 24) & 3;
                a00 += (v0 == 0) ? e4.x : 0.f; a01 += (v0 == 1) ? e4.x : 0.f; a02 += (v0 == 2) ? e4.x : 0.f;
                a00 += (v1 == 0) ? e4.y : 0.f; a01 += (v1 == 1) ? e4.y : 0.f; a02 += (v1 == 2) ? e4.y : 0.f;
                a00 += (v2 == 0) ? e4.z : 0.f; a01 += (v2 == 1) ? e4.z : 0.f; a02 += (v2 == 2) ? e4.z : 0.f;
                a00 += (v3 == 0) ? e4.w : 0.f; a01 += (v3 == 1) ? e4.w : 0.f; a02 += (v3 == 2) ? e4.w : 0.f;
            }
            if (g < 6) {
                {
                    unsigned tw = __funnelshift_r(u0, u1, 8);
                    int v0 = tw & 3, v1 = (tw >> 8) & 3, v2 = (tw >> 16) & 3, v3 = (tw >> 24) & 3;
                    a10 += (v0 == 0) ? e4.x : 0.f; a11 += (v0 == 1) ? e4.x : 0.f; a12 += (v0 == 2) ? e4.x : 0.f;
                    a10 += (v1 == 0) ? e4.y : 0.f; a11 += (v1 == 1) ? e4.y : 0.f; a12 += (v1 == 2) ? e4.y : 0.f;
                    a10 += (v2 == 0) ? e4.z : 0.f; a11 += (v2 == 1) ? e4.z : 0.f; a12 += (v2 == 2) ? e4.z : 0.f;
                    a10 += (v3 == 0) ? e4.w : 0.f; a11 += (v3 == 1) ? e4.w : 0.f; a12 += (v3 == 2) ? e4.w : 0.f;
                }
                {
                    unsigned tw = __funnelshift_r(u0, u1, 16);
                    int v0 = tw & 3, v1 = (tw >> 8) & 3, v2 = (tw >> 16) & 3, v3 = (tw >> 24) & 3;
                    a20 += (v0 == 0) ? e4.x : 0.f; a21 += (v0 == 1) ? e4.x : 0.f; a22 += (v0 == 2) ? e4.x : 0.f;
                    a20 += (v1 == 0) ? e4.y : 0.f; a21 += (v1 == 1) ? e4.y : 0.f; a22 += (v1 == 2) ? e4.y : 0.f;
                    a20 += (v2 == 0) ? e4.z : 0.f; a21 += (v2 == 1) ? e4.z : 0.f; a22 += (v2 == 2) ? e4.z : 0.f;
                    a20 += (v3 == 0) ? e4.w : 0.f; a21 += (v3 == 1) ? e4.w : 0.f; a22 += (v3 == 2) ? e4.w : 0.f;
                }
                {
                    unsigned tw = __funnelshift_r(u0, u1, 24);
                    int v0 = tw & 3, v1 = (tw >> 8) & 3, v2 = (tw >> 16) & 3, v3 = (tw >> 24) & 3;
                    a30 += (v0 == 0) ? e4.x : 0.f; a31 += (v0 == 1) ? e4.x : 0.f; a32 += (v0 == 2) ? e4.x : 0.f;
                    a30 += (v1 == 0) ? e4.y : 0.f; a31 += (v1 == 1) ? e4.y : 0.f; a32 += (v1 == 2) ? e4.y : 0.f;
                    a30 += (v2 == 0) ? e4.z : 0.f; a31 += (v2 == 1) ? e4.z : 0.f; a32 += (v2 == 2) ? e4.z : 0.f;
                    a30 += (v3 == 0) ? e4.w : 0.f; a31 += (v3 == 1) ? e4.w : 0.f; a32 += (v3 == 2) ? e4.w : 0.f;
                }
            }
        }
        a00 = warp_sum(a00); a01 = warp_sum(a01); a02 = warp_sum(a02);
        if (g < 6) {
            a10 = warp_sum(a10); a11 = warp_sum(a11); a12 = warp_sum(a12);
            a20 = warp_sum(a20); a21 = warp_sum(a21); a22 = warp_sum(a22);
            a30 = warp_sum(a30); a31 = warp_sum(a31); a32 = warp_sum(a32);
        }
        if (lane == 0) {
            float* p = &part[(g * 4 + s) * 12];
            p[0] = a00; p[1]  = a01; p[2]  = a02;
            p[3] = a10; p[4]  = a11; p[5]  = a12;
            p[6] = a20; p[7]  = a21; p[8]  = a22;
            p[9] = a30; p[10] = a31; p[11] = a32;
        }
    }
    __syncthreads();
    if (tid < T_EFF) {
        const int t = tid, g = t >> 2, r = t & 3;
        float s0 = 0.f, s1 = 0.f, s2 = 0.f;
        #pragma unroll
        for (int s_ = 0; s_ < 4; s_++) {
            const float* p = &part[(g * 4 + s_) * 12 + r * 3];
            s0 += p[0]; s1 += p[1]; s2 += p[2];
        }
        As[t * 4 + 0] = s0; As[t * 4 + 1] = s1;
        As[t * 4 + 2] = s2; As[t * 4 + 3] = Z - s0 - s1 - s2;
    }
    __syncthreads();

    // sv[x] = beff[x] + invZ * sum_i A_i * G[i][x]
    {
        int pt = tid >> 7, x = tid & 127;
        int i0 = pt * 13, i1 = (pt == 7) ? 100 : i0 + 13;
        float acc = 0.f;
        for (int i = i0; i < i1; i++) acc += As[i] * d_G[i * D + x];
        sc[pt * 128 + x] = acc;
    }
    __syncthreads();
    if (tid < D) {
        float acc = 0.f;
        #pragma unroll
        for (int p = 0; p < 8; p++) acc += sc[p * 128 + tid];
        sv[tid] = d_beff[tid] + acc * invZ;
    }
    __syncthreads();

    // out = Wv @ sv + bv
    for (int c = warp; c < D; c += 32) {
        float s = 0.f;
        #pragma unroll
        for (int m = 0; m < 4; m++) { int x = lane + 32 * m; s += wv[c * D + x] * sv[x]; }
        s = warp_sum(s);
        if (lane == 0) out[b * D + c] = s + bv[c];
    }
}

// ---------------------------------------------------------------------------
extern "C" void kernel_launch(void* const* d_in, const int* in_sizes, int n_in,
                              void* d_out, int out_size) {
    const int*   tokens = (const int*)  d_in[0];
    const float* emb    = (const float*)d_in[1];
    const float* w1     = (const float*)d_in[2];
    const float* b1     = (const float*)d_in[3];
    const float* wr     = (const float*)d_in[4];
    const float* br     = (const float*)d_in[5];
    const float* wq     = (const float*)d_in[6];
    const float* bq     = (const float*)d_in[7];
    const float* wk     = (const float*)d_in[8];
    const float* wv     = (const float*)d_in[10];
    const float* bv     = (const float*)d_in[11];

    const float* w2 = wr;
    const float* w3 = wr + D * D * KS;
    const float* b2 = br;
    const float* b3 = br + D;

    k_pre1<<<128, 1024>>>(w1, emb);
    k_pre2<<<128, 1024>>>(w2, b1, b2);
    k_pre3<<<128, 1024>>>(w3, b3);
    k_main<<<BATCH, 1024>>>(tokens, wq, bq, wk, wv, bv, (float*)d_out);
}